// round 1
// baseline (speedup 1.0000x reference)
#include <cuda_runtime.h>

// NoQmix_74560632258885
//
// Algebraic identity: softmax(e, axis=1) is normalized over the same axis the
// final einsum ('bij,bj->b') sums over, so Σ_i attention[b,i,j] == 1 for every
// (b, j) — including fully-masked columns (uniform softmax still sums to 1).
// Therefore q_tot[b] = Σ_j agent_qs[b,j] exactly, independent of features,
// adj, states, W, a.
//
// Kernel: row-sum of agent_qs [B=4096, N=64] fp32 -> out [B] fp32.
// One warp per row; lane l loads float2 at column 2l; warp shuffle reduce.

__global__ void rowsum64_kernel(const float* __restrict__ qs,
                                float* __restrict__ out,
                                int rows) {
    int gwarp = (blockIdx.x * blockDim.x + threadIdx.x) >> 5;
    int lane  = threadIdx.x & 31;
    if (gwarp >= rows) return;

    // 64 floats per row, 32 lanes -> one float2 per lane, coalesced 256B/warp.
    const float2* row = reinterpret_cast<const float2*>(qs) + gwarp * 32;
    float2 v = row[lane];
    float s = v.x + v.y;

    #pragma unroll
    for (int off = 16; off > 0; off >>= 1)
        s += __shfl_xor_sync(0xffffffffu, s, off);

    if (lane == 0) out[gwarp] = s;
}

extern "C" void kernel_launch(void* const* d_in, const int* in_sizes, int n_in,
                              void* d_out, int out_size) {
    // metadata order: features[0], agent_qs[1], adj[2], states[3], W[4], a[5]
    const float* agent_qs = (const float*)d_in[1];
    float* out = (float*)d_out;

    int rows = out_size;            // B = 4096 (output is B x 1 x 1)
    int threads = 256;              // 8 warps per block
    int blocks = (rows * 32 + threads - 1) / threads;  // one warp per row

    rowsum64_kernel<<<blocks, threads>>>(agent_qs, out, rows);
}

// round 2
// speedup vs baseline: 1.0105x; 1.0105x over previous
#include <cuda_runtime.h>

// NoQmix_74560632258885
//
// Algebraic identity (verified R1, rel_err 1.7e-7): softmax(e, axis=1) is
// normalized over the same axis the final einsum ('bij,bj->b') sums over, so
// Σ_i attention[b,i,j] == 1 for every (b, j). Hence
//   q_tot[b] = Σ_j agent_qs[b,j]
// independent of features, adj, states, W, a.
//
// R2: latency-optimized row-sum of agent_qs [B=4096, N=64] fp32.
// 4 threads per row; each thread issues 4 independent LDG.128 (64B contiguous,
// MLP=4) covering 16 floats, then a 2-step shfl reduction over 4 lanes.
// Grid: 4096 rows * 4 threads / 256 = 64 blocks.

__global__ void rowsum64_mlp4_kernel(const float4* __restrict__ qs4,
                                     float* __restrict__ out,
                                     int rows) {
    int t = blockIdx.x * blockDim.x + threadIdx.x;   // global thread id
    int row = t >> 2;                                 // 4 threads per row
    if (row >= rows) return;

    // Thread t owns float4 indices [4t, 4t+3] — 64B contiguous.
    const float4* p = qs4 + 4 * t;
    float4 v0 = p[0];
    float4 v1 = p[1];
    float4 v2 = p[2];
    float4 v3 = p[3];

    float s = (v0.x + v0.y) + (v0.z + v0.w)
            + (v1.x + v1.y) + (v1.z + v1.w)
            + (v2.x + v2.y) + (v2.z + v2.w)
            + (v3.x + v3.y) + (v3.z + v3.w);

    // Reduce across the 4 lanes of this row (lanes are consecutive in-warp).
    s += __shfl_xor_sync(0xffffffffu, s, 2);
    s += __shfl_xor_sync(0xffffffffu, s, 1);

    if ((t & 3) == 0) out[row] = s;
}

extern "C" void kernel_launch(void* const* d_in, const int* in_sizes, int n_in,
                              void* d_out, int out_size) {
    // metadata order: features[0], agent_qs[1], adj[2], states[3], W[4], a[5]
    const float4* agent_qs4 = (const float4*)d_in[1];
    float* out = (float*)d_out;

    int rows = out_size;                 // B = 4096
    int total_threads = rows * 4;        // 4 threads per row
    int threads = 256;
    int blocks = (total_threads + threads - 1) / threads;   // 64

    rowsum64_mlp4_kernel<<<blocks, threads>>>(agent_qs4, out, rows);
}